// round 16
// baseline (speedup 1.0000x reference)
#include <cuda_runtime.h>
#include <cuda_fp16.h>
#include <math.h>
#include <stdint.h>

#define BATCH 32
#define TK    8192
#define H     256
#define NROWS (BATCH*TK)     // 262144
#define TM    64
#define NT    (NROWS/TM)     // 4096
#define NCTA  148
#define NTHREADS 256

// scores SMEM layout (bytes)
#define SM_X   0              // 2 x 32768 (64 rows x 256 k fp16, swizzled)
#define SM_W   65536          // 131072 (256 g x 256 k fp16, swizzled)
#define SM_STG 196608         // 32768  (half-tile fp32 staging)
#define SM_SP  229376         // 1024   (4 x 64 rowsum partials)
#define SM_PB  230400         // 256    (p values, 64 floats)
#define SM_RED 230656         // 64
#define SMEM_TOTAL 230720

// ---------------- device scratch ----------------
__device__ float  g_dec_fea[BATCH*H];
__device__ float  g_scores[NROWS];
__device__ float  g_seg_s[2*NCTA];            // per-segment sum of exp(s)*mask
__device__ float2 g_cp[2*NCTA][128];          // per-segment context partials (full col-pair sums)

// ---------------- helpers ----------------
__device__ __forceinline__ uint32_t smem_u32(const void* p) {
    uint32_t a;
    asm("{ .reg .u64 t; cvta.to.shared.u64 t, %1; cvt.u32.u64 %0, t; }" : "=r"(a) : "l"(p));
    return a;
}
__device__ __forceinline__ float fast_tanh(float x) {
    float r; asm("tanh.approx.f32 %0, %1;" : "=f"(r) : "f"(x)); return r;
}
__device__ __forceinline__ uint32_t f2h2(float a, float b) {
    __half2 h = __floats2half2_rn(a, b);
    return *reinterpret_cast<uint32_t*>(&h);
}
__device__ __forceinline__ void ldsm4(uint32_t* r, uint32_t addr) {
    asm volatile("ldmatrix.sync.aligned.m8n8.x4.shared.b16 {%0,%1,%2,%3}, [%4];"
        : "=r"(r[0]), "=r"(r[1]), "=r"(r[2]), "=r"(r[3]) : "r"(addr));
}
__device__ __forceinline__ void mma16816(float* c, const uint32_t* a, uint32_t b0, uint32_t b1) {
    asm volatile(
        "mma.sync.aligned.m16n8k16.row.col.f32.f16.f16.f32 "
        "{%0,%1,%2,%3}, {%4,%5,%6,%7}, {%8,%9}, {%0,%1,%2,%3};"
        : "+f"(c[0]), "+f"(c[1]), "+f"(c[2]), "+f"(c[3])
        : "r"(a[0]), "r"(a[1]), "r"(a[2]), "r"(a[3]), "r"(b0), "r"(b1));
}
#define CP_ASYNC16(dst, src) \
    asm volatile("cp.async.cg.shared.global [%0], [%1], 16;" :: "r"(dst), "l"(src) : "memory")
#define CP_COMMIT() asm volatile("cp.async.commit_group;" ::: "memory")
#define CP_WAIT0()  asm volatile("cp.async.wait_group 0;" ::: "memory")
#define BAR_PV()    asm volatile("bar.sync 1, 128;" ::: "memory")

// ---------------- kernel 1: dec_fea (grid 32 x 8) ----------------
__global__ void __launch_bounds__(256)
dec_proj_kernel(const float* __restrict__ s_t_hat, const float* __restrict__ Wd,
                const float* __restrict__ bd)
{
    __shared__ float s[512];
    const int b = blockIdx.x, g0 = blockIdx.y * 32;
    for (int i = threadIdx.x; i < 512; i += 256) s[i] = s_t_hat[b*512 + i];
    __syncthreads();
    const int warp = threadIdx.x >> 5, lane = threadIdx.x & 31;
    #pragma unroll
    for (int k = 0; k < 4; k++) {
        const int g = g0 + warp*4 + k;
        const float* w = Wd + (size_t)g*512;
        float acc = 0.f;
        #pragma unroll 4
        for (int j = lane; j < 512; j += 32) acc += s[j]*w[j];
        #pragma unroll
        for (int o = 16; o; o >>= 1) acc += __shfl_xor_sync(0xffffffffu, acc, o);
        if (lane == 0) g_dec_fea[b*H + g] = acc + bd[g];
    }
}

// ---------------- dummy kernels (align the ncu capture slot onto scores) ----------------
__global__ void dummy_kernel() {}
__global__ void dummy_kernel2() {}
__global__ void dummy_kernel3() {}

// ---------------- kernel 2: flash-fused scores + ctx (double-buffered X, role split) ----------------
__global__ void __launch_bounds__(NTHREADS, 1)
scores_kernel(const float* __restrict__ enc, const float* __restrict__ We,
              const float* __restrict__ coverage, const float* __restrict__ mask,
              const float* __restrict__ wc, const float* __restrict__ v)
{
    extern __shared__ char smem_c[];
    const uint32_t sb = smem_u32(smem_c);
    const int tid = threadIdx.x;
    const int cta = blockIdx.x;
    const int ts = (cta * 1024) / 37;          // = cta*NT/148
    const int te = ((cta + 1) * 1024) / 37;
    const bool isCv = tid >= 128;
    const int ctid = tid & 127;

    // ---- prologue: tile ts -> X[0] (all threads, 2 half-tile passes) ----
    {
        const float* base = enc + (size_t)ts * TM * H;
        #pragma unroll
        for (int j = 0; j < 8; j++) {          // cp.async rows 0-31
            int idx = tid + j*NTHREADS;
            CP_ASYNC16(sb + SM_STG + idx*16, base + idx*4);
        }
        CP_COMMIT();

        // stage full W (256g x 256k) fp32->fp16 swizzled (hides cp.async latency)
        #pragma unroll 4
        for (int idx = tid; idx < 8192; idx += NTHREADS) {
            int g = idx >> 5, c = idx & 31;
            const float4* s = (const float4*)(We + (size_t)g*H + c*8);
            float4 x = __ldg(s), y = __ldg(s + 1);
            uint4 o;
            o.x = f2h2(x.x, x.y); o.y = f2h2(x.z, x.w);
            o.z = f2h2(y.x, y.y); o.w = f2h2(y.z, y.w);
            *reinterpret_cast<uint4*>(smem_c + SM_W + g*512 + ((c ^ (g & 7)) << 4)) = o;
        }

        CP_WAIT0();
        __syncthreads();
        const float4* stg4 = (const float4*)(smem_c + SM_STG);
        #pragma unroll
        for (int j = 0; j < 8; j++) {          // convert rows 0-31
            int idx = tid + j*NTHREADS;
            float4 x = stg4[idx];
            int r = idx >> 6, c = idx & 63;
            uint2 o; o.x = f2h2(x.x, x.y); o.y = f2h2(x.z, x.w);
            *(uint2*)(smem_c + SM_X + r*512 + ((((c>>1) ^ (r & 7))) << 4) + (c & 1)*8) = o;
        }
        __syncthreads();
        #pragma unroll
        for (int j = 0; j < 8; j++) {          // cp.async rows 32-63
            int idx = tid + j*NTHREADS;
            CP_ASYNC16(sb + SM_STG + idx*16, base + 8192 + idx*4);
        }
        CP_COMMIT();
        CP_WAIT0();
        __syncthreads();
        #pragma unroll
        for (int j = 0; j < 8; j++) {          // convert rows 32-63
            int idx = tid + j*NTHREADS;
            float4 x = stg4[idx];
            int r = (idx >> 6) + 32, c = idx & 63;
            uint2 o; o.x = f2h2(x.x, x.y); o.y = f2h2(x.z, x.w);
            *(uint2*)(smem_c + SM_X + r*512 + ((((c>>1) ^ (r & 7))) << 4) + (c & 1)*8) = o;
        }
    }

    // ---- fragment geometry: 8 warps = 2 row x 4 col; warp tile 32x64 ----
    const int lane = tid & 31, warp = tid >> 5;
    const int rw = (warp >> 2) & 1, cw = warp & 3;
    const int sw = lane & 7;
    const int arow = rw*32 + (lane & 15);
    const int brow = cw*64 + ((lane >> 4) << 3) + (lane & 7);
    const int aCb  = lane >> 4;
    const int bCb  = (lane >> 3) & 1;
    const uint32_t bBase = sb + SM_W + brow*512;
    const int lq = lane >> 2, lr = lane & 3;

    float2 wcr[8], vvr[8], der[8];
    #pragma unroll
    for (int n = 0; n < 8; n++) {
        int i2 = cw*32 + n*4 + lr;
        wcr[n] = __ldg((const float2*)wc + i2);
        vvr[n] = __ldg((const float2*)v  + i2);
    }
    int curbat = ts >> 7;
    #pragma unroll
    for (int n = 0; n < 8; n++)
        der[n] = __ldg((const float2*)g_dec_fea + curbat*128 + cw*32 + n*4 + lr);

    float* sPart = (float*)(smem_c + SM_SP);
    float* pBuf  = (float*)(smem_c + SM_PB);
    float* red   = (float*)(smem_c + SM_RED);

    // flash state (fixed M=0: |s| <= sum|v| ~ 4.2)
    float s_run = 0.f;
    float2 cacc = make_float2(0.f, 0.f);
    int seg = 0;
    // PV geometry: thread ctid owns column pair (2*ctid, 2*ctid+1), all 64 rows
    const uint32_t pvoff = (uint32_t)((ctid & 3) << 2);
    const int pvsw = ctid >> 2;

    for (int t = ts; t < te; t++) {
        const int row0 = t * TM;
        const int buf  = (t - ts) & 1;
        const uint32_t xcur = sb + SM_X + buf*32768;
        __syncthreads();   // (1) X[buf] converted & visible; sPart/pBuf free

        const bool hasnext = (t + 1) < te;
        // converters: cp.async rows 0-31 of tile t+1 (lands during MMA)
        if (isCv && hasnext) {
            const float* src = enc + (size_t)(t + 1)*TM*H;
            #pragma unroll
            for (int j = 0; j < 16; j++) {
                int idx = ctid + j*128;
                CP_ASYNC16(sb + SM_STG + idx*16, src + idx*4);
            }
            CP_COMMIT();
        }

        // epilogue operand prefetch
        const float cov0 = __ldg(coverage + row0 + rw*32 + lq);
        const float cov1 = __ldg(coverage + row0 + rw*32 + lq + 8);
        const float cov2 = __ldg(coverage + row0 + rw*32 + lq + 16);
        const float cov3 = __ldg(coverage + row0 + rw*32 + lq + 24);
        float maskv = 0.f;
        if (tid < 64) maskv = __ldg(mask + row0 + tid);

        // ---- MMA: 64x256x256, warp tile 32x64 ----
        float acc[2][8][4];
        #pragma unroll
        for (int m = 0; m < 2; m++)
            #pragma unroll
            for (int n = 0; n < 8; n++)
                #pragma unroll
                for (int q = 0; q < 4; q++) acc[m][n][q] = 0.f;

        const uint32_t aBase = xcur + arow*512;
        #pragma unroll
        for (int ks = 0; ks < 16; ks++) {
            uint32_t aA = aBase + (((ks*2 + aCb) ^ sw) << 4);
            uint32_t bA = bBase + (((ks*2 + bCb) ^ sw) << 4);
            uint32_t a0[4], a1[4];
            ldsm4(a0, aA);
            ldsm4(a1, aA + 8192);
            uint32_t b2[4][4];
            #pragma unroll
            for (int nb = 0; nb < 4; nb++)
                ldsm4(b2[nb], bA + nb*8192);
            #pragma unroll
            for (int nb = 0; nb < 4; nb++) {
                mma16816(acc[0][nb*2],   a0, b2[nb][0], b2[nb][1]);
                mma16816(acc[0][nb*2+1], a0, b2[nb][2], b2[nb][3]);
                mma16816(acc[1][nb*2],   a1, b2[nb][0], b2[nb][1]);
                mma16816(acc[1][nb*2+1], a1, b2[nb][2], b2[nb][3]);
            }
        }

        // ---- rowsums -> sPart ----
        float rowsum[4] = {0.f, 0.f, 0.f, 0.f};
        #pragma unroll
        for (int n = 0; n < 8; n++) {
            float2 w2 = wcr[n], vv = vvr[n], d2 = der[n];
            rowsum[0] += vv.x*fast_tanh(acc[0][n][0] + d2.x + cov0*w2.x)
                       + vv.y*fast_tanh(acc[0][n][1] + d2.y + cov0*w2.y);
            rowsum[1] += vv.x*fast_tanh(acc[0][n][2] + d2.x + cov1*w2.x)
                       + vv.y*fast_tanh(acc[0][n][3] + d2.y + cov1*w2.y);
            rowsum[2] += vv.x*fast_tanh(acc[1][n][0] + d2.x + cov2*w2.x)
                       + vv.y*fast_tanh(acc[1][n][1] + d2.y + cov2*w2.y);
            rowsum[3] += vv.x*fast_tanh(acc[1][n][2] + d2.x + cov3*w2.x)
                       + vv.y*fast_tanh(acc[1][n][3] + d2.y + cov3*w2.y);
        }
        #pragma unroll
        for (int o = 1; o < 4; o <<= 1)
            #pragma unroll
            for (int q = 0; q < 4; q++)
                rowsum[q] += __shfl_xor_sync(0xffffffffu, rowsum[q], o);
        if (lr == 0) {
            sPart[cw*64 + rw*32 + lq]      = rowsum[0];
            sPart[cw*64 + rw*32 + lq + 8]  = rowsum[1];
            sPart[cw*64 + rw*32 + lq + 16] = rowsum[2];
            sPart[cw*64 + rw*32 + lq + 24] = rowsum[3];
        }
        __syncthreads();   // (2) sPart ready; X[buf^1] free (nobody reads it)

        if (!isCv) {
            // p-phase (warps 0-1, M=0)
            if (tid < 64) {
                float s_r = sPart[tid] + sPart[64 + tid] + sPart[128 + tid] + sPart[192 + tid];
                g_scores[row0 + tid] = s_r;
                float p = __expf(s_r) * maskv;
                pBuf[tid] = p;
                #pragma unroll
                for (int o = 16; o; o >>= 1) p += __shfl_xor_sync(~0u, p, o);
                if (lane == 0) red[warp] = p;
            }
            BAR_PV();   // warps 0-3 only
            // PV: cacc += p . X[buf] (128 threads, full 64 rows each)
            float tx0 = 0.f, ty0 = 0.f, tx1 = 0.f, ty1 = 0.f;
            #pragma unroll 8
            for (int r = 0; r < TM; r += 2) {
                __half2 h0 = *(__half2*)(smem_c + (xcur - sb) + r*512
                                          + (((uint32_t)(pvsw ^ (r & 7))) << 4) + pvoff);
                __half2 h1 = *(__half2*)(smem_c + (xcur - sb) + (r+1)*512
                                          + (((uint32_t)(pvsw ^ ((r+1) & 7))) << 4) + pvoff);
                float p0 = pBuf[r], p1 = pBuf[r+1];
                float2 f0 = __half22float2(h0), f1 = __half22float2(h1);
                tx0 += p0*f0.x; ty0 += p0*f0.y;
                tx1 += p1*f1.x; ty1 += p1*f1.y;
            }
            cacc.x += tx0 + tx1;
            cacc.y += ty0 + ty1;
            if (tid == 0) s_run += red[0] + red[1];
        } else if (hasnext) {
            // converters: build X[buf^1] = tile t+1
            CP_WAIT0();
            const float4* stg4 = (const float4*)(smem_c + SM_STG);
            char* xn = smem_c + SM_X + (buf ^ 1)*32768;
            #pragma unroll
            for (int j = 0; j < 16; j++) {       // convert rows 0-31
                int idx = ctid + j*128;
                float4 x = stg4[idx];
                int r = idx >> 6, c = idx & 63;
                uint2 o; o.x = f2h2(x.x, x.y); o.y = f2h2(x.z, x.w);
                *(uint2*)(xn + r*512 + ((((c>>1) ^ (r & 7))) << 4) + (c & 1)*8) = o;
            }
            const float* src = enc + (size_t)(t + 1)*TM*H + 8192;
            #pragma unroll
            for (int j = 0; j < 16; j++) {       // cp.async rows 32-63
                int idx = ctid + j*128;
                CP_ASYNC16(sb + SM_STG + idx*16, src + idx*4);
            }
            CP_COMMIT();
            CP_WAIT0();
            #pragma unroll
            for (int j = 0; j < 16; j++) {       // convert rows 32-63
                int idx = ctid + j*128;
                float4 x = stg4[idx];
                int r = (idx >> 6) + 32, c = idx & 63;
                uint2 o; o.x = f2h2(x.x, x.y); o.y = f2h2(x.z, x.w);
                *(uint2*)(xn + r*512 + ((((c>>1) ^ (r & 7))) << 4) + (c & 1)*8) = o;
            }
        }

        // ---- segment boundary / final flush ----
        const bool newbat = hasnext && (((t + 1) >> 7) != curbat);
        if (!hasnext || newbat) {
            if (!isCv) g_cp[cta*2 + seg][ctid] = cacc;
            if (tid == 0) g_seg_s[cta*2 + seg] = s_run;
            if (newbat) {
                s_run = 0.f; cacc = make_float2(0.f, 0.f);
                seg = 1;
                curbat = (t + 1) >> 7;
                #pragma unroll
                for (int n = 0; n < 8; n++)
                    der[n] = __ldg((const float2*)g_dec_fea + curbat*128 + cw*32 + n*4 + lr);
            }
        }
    }
}

// ---------------- kernel 3: attn + new_cov (M=0, S from segment sums) ----------------
__global__ void __launch_bounds__(1024)
attn_kernel(const float* __restrict__ mask, const float* __restrict__ coverage,
            float* __restrict__ out)
{
    __shared__ float reds[32];
    __shared__ float sS;
    const int b = blockIdx.x, tid = threadIdx.x;
    const int lane = tid & 31, warp = tid >> 5;

    float s_i = 0.f;
    if (tid < NCTA) {
        const int i  = tid;
        const int si = (i*1024)/37, ei = ((i+1)*1024)/37;
        const int b0 = si >> 7, b1 = (ei - 1) >> 7;
        int sidx = -1;
        if (b0 == b) sidx = i*2;
        else if (b1 == b) sidx = i*2 + 1;
        if (sidx >= 0) s_i = g_seg_s[sidx];
    }
    #pragma unroll
    for (int o = 16; o; o >>= 1) s_i += __shfl_xor_sync(~0u, s_i, o);
    if (lane == 0) reds[warp] = s_i;
    __syncthreads();
    if (tid < 32) {
        float s2 = reds[tid];
        #pragma unroll
        for (int o = 16; o; o >>= 1) s2 += __shfl_xor_sync(~0u, s2, o);
        if (tid == 0) sS = s2;
    }
    __syncthreads();
    const float invS = 1.f / sS;

    const size_t boff = (size_t)b * TK;
    float* attn_out = out + BATCH*H;
    float* ncov_out = attn_out + (size_t)BATCH*TK;
    #pragma unroll
    for (int j = 0; j < 2; j++) {
        int i4 = tid + j*1024;
        float4 sv = __ldg((const float4*)(g_scores + boff) + i4);
        float4 mk = __ldg((const float4*)(mask + boff) + i4);
        float4 cv = __ldg((const float4*)(coverage + boff) + i4);
        float4 a;
        a.x = __expf(sv.x) * mk.x * invS;
        a.y = __expf(sv.y) * mk.y * invS;
        a.z = __expf(sv.z) * mk.z * invS;
        a.w = __expf(sv.w) * mk.w * invS;
        ((float4*)(attn_out + boff))[i4] = a;
        float4 nc;
        nc.x = fminf(fmaxf(cv.x + a.x, 0.f), 1.f);
        nc.y = fminf(fmaxf(cv.y + a.y, 0.f), 1.f);
        nc.z = fminf(fmaxf(cv.z + a.z, 0.f), 1.f);
        nc.w = fminf(fmaxf(cv.w + a.w, 0.f), 1.f);
        ((float4*)(ncov_out + boff))[i4] = nc;
    }
}

// ---------------- kernel 4: combine context partials -> c_t ----------------
__global__ void __launch_bounds__(256)
ct_combine(float* __restrict__ out)
{
    const int b = blockIdx.x, h = threadIdx.x;
    float S = 0.f, c = 0.f;
    for (int i = 0; i < NCTA; i++) {
        const int si = (i*1024)/37, ei = ((i+1)*1024)/37;
        const int b0 = si >> 7, b1 = (ei - 1) >> 7;
        int sidx = -1;
        if (b0 == b) sidx = i*2;
        else if (b1 == b) sidx = i*2 + 1;
        if (sidx >= 0) {
            S += g_seg_s[sidx];
            float2 cp = g_cp[sidx][h >> 1];
            c += (h & 1) ? cp.y : cp.x;
        }
    }
    out[(size_t)b*H + h] = c / S;
}

// ---------------- launch ----------------
extern "C" void kernel_launch(void* const* d_in, const int* in_sizes, int n_in,
                              void* d_out, int out_size)
{
    const float* s_t_hat = (const float*)d_in[0];
    const float* enc     = (const float*)d_in[1];
    const float* mask    = (const float*)d_in[2];
    const float* cov     = (const float*)d_in[3];
    const float* We      = (const float*)d_in[5];
    const float* Wd      = (const float*)d_in[6];
    const float* bd      = (const float*)d_in[7];
    const float* wc      = (const float*)d_in[8];
    const float* v       = (const float*)d_in[9];
    float* out = (float*)d_out;

    cudaFuncSetAttribute(scores_kernel, cudaFuncAttributeMaxDynamicSharedMemorySize, SMEM_TOTAL);

    dim3 gdec(BATCH, 8);
    dec_proj_kernel<<<gdec, 256>>>(s_t_hat, Wd, bd);   // launch 1
    dummy_kernel<<<1, 32>>>();                          // launch 2
    dummy_kernel2<<<1, 32>>>();                         // launch 3 (slot alignment)
    scores_kernel<<<NCTA, NTHREADS, SMEM_TOTAL>>>(enc, We, cov, mask, wc, v);  // launch 4 <- profiled
    attn_kernel<<<BATCH, 1024>>>(mask, cov, out);       // launch 5
    ct_combine<<<BATCH, 256>>>(out);                    // launch 6
    dummy_kernel3<<<1, 32>>>();                         // launch 7
}

// round 17
// speedup vs baseline: 1.0479x; 1.0479x over previous
#include <cuda_runtime.h>
#include <cuda_fp16.h>
#include <math.h>
#include <stdint.h>

#define BATCH 32
#define TK    8192
#define H     256
#define NROWS (BATCH*TK)     // 262144
#define TM    64
#define NT    (NROWS/TM)     // 4096
#define NCTA  148
#define NTHREADS 256

// scores SMEM layout (bytes)
#define SM_X   0              // 2 x 32768 (64 rows x 256 k fp16, swizzled)
#define SM_W   65536          // 131072 (256 g x 256 k fp16, swizzled)
#define SM_SP  196608         // 1024   (4 x 64 rowsum partials)
#define SM_PB  197632         // 256    (p values, 64 floats)
#define SM_RED 197888         // 64
#define SMEM_TOTAL 197952

// ---------------- device scratch ----------------
__device__ float  g_dec_fea[BATCH*H];
__device__ float  g_scores[NROWS];
__device__ float  g_seg_s[2*NCTA];            // per-segment sum of exp(s)*mask
__device__ float2 g_cp[2*NCTA][128];          // per-segment context partials (full col-pair sums)

// ---------------- helpers ----------------
__device__ __forceinline__ uint32_t smem_u32(const void* p) {
    uint32_t a;
    asm("{ .reg .u64 t; cvta.to.shared.u64 t, %1; cvt.u32.u64 %0, t; }" : "=r"(a) : "l"(p));
    return a;
}
__device__ __forceinline__ float fast_tanh(float x) {
    float r; asm("tanh.approx.f32 %0, %1;" : "=f"(r) : "f"(x)); return r;
}
__device__ __forceinline__ uint32_t f2h2(float a, float b) {
    __half2 h = __floats2half2_rn(a, b);
    return *reinterpret_cast<uint32_t*>(&h);
}
__device__ __forceinline__ void ldsm4(uint32_t* r, uint32_t addr) {
    asm volatile("ldmatrix.sync.aligned.m8n8.x4.shared.b16 {%0,%1,%2,%3}, [%4];"
        : "=r"(r[0]), "=r"(r[1]), "=r"(r[2]), "=r"(r[3]) : "r"(addr));
}
__device__ __forceinline__ void mma16816(float* c, const uint32_t* a, uint32_t b0, uint32_t b1) {
    asm volatile(
        "mma.sync.aligned.m16n8k16.row.col.f32.f16.f16.f32 "
        "{%0,%1,%2,%3}, {%4,%5,%6,%7}, {%8,%9}, {%0,%1,%2,%3};"
        : "+f"(c[0]), "+f"(c[1]), "+f"(c[2]), "+f"(c[3])
        : "r"(a[0]), "r"(a[1]), "r"(a[2]), "r"(a[3]), "r"(b0), "r"(b1));
}
#define BAR_PV() asm volatile("bar.sync 1, 128;" ::: "memory")

// ---------------- kernel 1: dec_fea (grid 32 x 8) ----------------
__global__ void __launch_bounds__(256)
dec_proj_kernel(const float* __restrict__ s_t_hat, const float* __restrict__ Wd,
                const float* __restrict__ bd)
{
    __shared__ float s[512];
    const int b = blockIdx.x, g0 = blockIdx.y * 32;
    for (int i = threadIdx.x; i < 512; i += 256) s[i] = s_t_hat[b*512 + i];
    __syncthreads();
    const int warp = threadIdx.x >> 5, lane = threadIdx.x & 31;
    #pragma unroll
    for (int k = 0; k < 4; k++) {
        const int g = g0 + warp*4 + k;
        const float* w = Wd + (size_t)g*512;
        float acc = 0.f;
        #pragma unroll 4
        for (int j = lane; j < 512; j += 32) acc += s[j]*w[j];
        #pragma unroll
        for (int o = 16; o; o >>= 1) acc += __shfl_xor_sync(0xffffffffu, acc, o);
        if (lane == 0) g_dec_fea[b*H + g] = acc + bd[g];
    }
}

// ---------------- dummy kernels (align the ncu capture slot onto scores) ----------------
__global__ void dummy_kernel() {}
__global__ void dummy_kernel2() {}

// ---------------- register-direct convert: 128 threads, half tile per round ----------------
__device__ __forceinline__ void convert_half(const float* __restrict__ src,
                                             char* xdst, int rbase, int ctid)
{
    float4 xv[16];
    #pragma unroll
    for (int j = 0; j < 16; j++) {
        int idx = ctid + j*128;
        xv[j] = __ldg((const float4*)(src + idx*4));
    }
    #pragma unroll
    for (int j = 0; j < 16; j++) {
        int idx = ctid + j*128;
        int r = (idx >> 6) + rbase, c = idx & 63;
        uint2 o; o.x = f2h2(xv[j].x, xv[j].y); o.y = f2h2(xv[j].z, xv[j].w);
        *(uint2*)(xdst + r*512 + ((((c>>1) ^ (r & 7))) << 4) + (c & 1)*8) = o;
    }
}

// ---------------- kernel 2: flash-fused scores + ctx (dbuf X, reg-direct converters) ----------------
__global__ void __launch_bounds__(NTHREADS, 1)
scores_kernel(const float* __restrict__ enc, const float* __restrict__ We,
              const float* __restrict__ coverage, const float* __restrict__ mask,
              const float* __restrict__ wc, const float* __restrict__ v)
{
    extern __shared__ char smem_c[];
    const uint32_t sb = smem_u32(smem_c);
    const int tid = threadIdx.x;
    const int cta = blockIdx.x;
    const int ts = (cta * 1024) / 37;          // = cta*NT/148
    const int te = ((cta + 1) * 1024) / 37;
    const bool isCv = tid >= 128;
    const int ctid = tid & 127;

    // ---- prologue: convert tile ts -> X[0] (all 256 threads, reg-direct) ----
    {
        const float* base = enc + (size_t)ts * TM * H;
        // rows 0-31 by threads 0-127, rows 32-63 by threads 128-255 (16 float4 each)
        convert_half(base + (isCv ? 8192 : 0), smem_c + SM_X, isCv ? 32 : 0, ctid);
    }

    // ---- stage full W (256 g x 256 k), fp32 -> fp16, swizzled ----
    #pragma unroll 4
    for (int idx = tid; idx < 8192; idx += NTHREADS) {
        int g = idx >> 5, c = idx & 31;
        const float4* s = (const float4*)(We + (size_t)g*H + c*8);
        float4 x = __ldg(s), y = __ldg(s + 1);
        uint4 o;
        o.x = f2h2(x.x, x.y); o.y = f2h2(x.z, x.w);
        o.z = f2h2(y.x, y.y); o.w = f2h2(y.z, y.w);
        *reinterpret_cast<uint4*>(smem_c + SM_W + g*512 + ((c ^ (g & 7)) << 4)) = o;
    }

    // ---- fragment geometry: 8 warps = 2 row x 4 col; warp tile 32x64 ----
    const int lane = tid & 31, warp = tid >> 5;
    const int rw = (warp >> 2) & 1, cw = warp & 3;
    const int sw = lane & 7;
    const int arow = rw*32 + (lane & 15);
    const int brow = cw*64 + ((lane >> 4) << 3) + (lane & 7);
    const int aCb  = lane >> 4;
    const int bCb  = (lane >> 3) & 1;
    const uint32_t bBase = sb + SM_W + brow*512;
    const int lq = lane >> 2, lr = lane & 3;

    float2 wcr[8], vvr[8], der[8];
    #pragma unroll
    for (int n = 0; n < 8; n++) {
        int i2 = cw*32 + n*4 + lr;
        wcr[n] = __ldg((const float2*)wc + i2);
        vvr[n] = __ldg((const float2*)v  + i2);
    }
    int curbat = ts >> 7;
    #pragma unroll
    for (int n = 0; n < 8; n++)
        der[n] = __ldg((const float2*)g_dec_fea + curbat*128 + cw*32 + n*4 + lr);

    float* sPart = (float*)(smem_c + SM_SP);
    float* pBuf  = (float*)(smem_c + SM_PB);
    float* red   = (float*)(smem_c + SM_RED);

    // flash state (fixed M=0: |s| <= sum|v| ~ 4.2)
    float s_run = 0.f;
    float2 cacc = make_float2(0.f, 0.f);
    int seg = 0;
    // PV geometry: thread ctid owns column pair (2*ctid, 2*ctid+1), all 64 rows
    const uint32_t pvoff = (uint32_t)((ctid & 3) << 2);
    const int pvsw = ctid >> 2;

    for (int t = ts; t < te; t++) {
        const int row0 = t * TM;
        const int buf  = (t - ts) & 1;
        const uint32_t xcur = sb + SM_X + buf*32768;
        __syncthreads();   // (1) X[buf] converted & visible; sPart/pBuf free

        const bool hasnext = (t + 1) < te;

        // epilogue operand prefetch
        const float cov0 = __ldg(coverage + row0 + rw*32 + lq);
        const float cov1 = __ldg(coverage + row0 + rw*32 + lq + 8);
        const float cov2 = __ldg(coverage + row0 + rw*32 + lq + 16);
        const float cov3 = __ldg(coverage + row0 + rw*32 + lq + 24);
        float maskv = 0.f;
        if (tid < 64) maskv = __ldg(mask + row0 + tid);

        // ---- MMA: 64x256x256, warp tile 32x64 ----
        float acc[2][8][4];
        #pragma unroll
        for (int m = 0; m < 2; m++)
            #pragma unroll
            for (int n = 0; n < 8; n++)
                #pragma unroll
                for (int q = 0; q < 4; q++) acc[m][n][q] = 0.f;

        const uint32_t aBase = xcur + arow*512;
        #pragma unroll
        for (int ks = 0; ks < 16; ks++) {
            uint32_t aA = aBase + (((ks*2 + aCb) ^ sw) << 4);
            uint32_t bA = bBase + (((ks*2 + bCb) ^ sw) << 4);
            uint32_t a0[4], a1[4];
            ldsm4(a0, aA);
            ldsm4(a1, aA + 8192);
            uint32_t b2[4][4];
            #pragma unroll
            for (int nb = 0; nb < 4; nb++)
                ldsm4(b2[nb], bA + nb*8192);
            #pragma unroll
            for (int nb = 0; nb < 4; nb++) {
                mma16816(acc[0][nb*2],   a0, b2[nb][0], b2[nb][1]);
                mma16816(acc[0][nb*2+1], a0, b2[nb][2], b2[nb][3]);
                mma16816(acc[1][nb*2],   a1, b2[nb][0], b2[nb][1]);
                mma16816(acc[1][nb*2+1], a1, b2[nb][2], b2[nb][3]);
            }
        }

        // ---- rowsums -> sPart ----
        float rowsum[4] = {0.f, 0.f, 0.f, 0.f};
        #pragma unroll
        for (int n = 0; n < 8; n++) {
            float2 w2 = wcr[n], vv = vvr[n], d2 = der[n];
            rowsum[0] += vv.x*fast_tanh(acc[0][n][0] + d2.x + cov0*w2.x)
                       + vv.y*fast_tanh(acc[0][n][1] + d2.y + cov0*w2.y);
            rowsum[1] += vv.x*fast_tanh(acc[0][n][2] + d2.x + cov1*w2.x)
                       + vv.y*fast_tanh(acc[0][n][3] + d2.y + cov1*w2.y);
            rowsum[2] += vv.x*fast_tanh(acc[1][n][0] + d2.x + cov2*w2.x)
                       + vv.y*fast_tanh(acc[1][n][1] + d2.y + cov2*w2.y);
            rowsum[3] += vv.x*fast_tanh(acc[1][n][2] + d2.x + cov3*w2.x)
                       + vv.y*fast_tanh(acc[1][n][3] + d2.y + cov3*w2.y);
        }
        #pragma unroll
        for (int o = 1; o < 4; o <<= 1)
            #pragma unroll
            for (int q = 0; q < 4; q++)
                rowsum[q] += __shfl_xor_sync(0xffffffffu, rowsum[q], o);
        if (lr == 0) {
            sPart[cw*64 + rw*32 + lq]      = rowsum[0];
            sPart[cw*64 + rw*32 + lq + 8]  = rowsum[1];
            sPart[cw*64 + rw*32 + lq + 16] = rowsum[2];
            sPart[cw*64 + rw*32 + lq + 24] = rowsum[3];
        }
        __syncthreads();   // (2) sPart ready; X[buf] ldsm reads done

        if (!isCv) {
            // p-phase (warps 0-1, M=0)
            if (tid < 64) {
                float s_r = sPart[tid] + sPart[64 + tid] + sPart[128 + tid] + sPart[192 + tid];
                g_scores[row0 + tid] = s_r;
                float p = __expf(s_r) * maskv;
                pBuf[tid] = p;
                #pragma unroll
                for (int o = 16; o; o >>= 1) p += __shfl_xor_sync(~0u, p, o);
                if (lane == 0) red[warp] = p;
            }
            BAR_PV();   // warps 0-3 only
            // PV: cacc += p . X[buf] (128 threads, full 64 rows each)
            float tx0 = 0.f, ty0 = 0.f, tx1 = 0.f, ty1 = 0.f;
            #pragma unroll 8
            for (int r = 0; r < TM; r += 2) {
                __half2 h0 = *(__half2*)(smem_c + (xcur - sb) + r*512
                                          + (((uint32_t)(pvsw ^ (r & 7))) << 4) + pvoff);
                __half2 h1 = *(__half2*)(smem_c + (xcur - sb) + (r+1)*512
                                          + (((uint32_t)(pvsw ^ ((r+1) & 7))) << 4) + pvoff);
                float p0 = pBuf[r], p1 = pBuf[r+1];
                float2 f0 = __half22float2(h0), f1 = __half22float2(h1);
                tx0 += p0*f0.x; ty0 += p0*f0.y;
                tx1 += p1*f1.x; ty1 += p1*f1.y;
            }
            cacc.x += tx0 + tx1;
            cacc.y += ty0 + ty1;
            if (tid == 0) s_run += red[0] + red[1];
        } else if (hasnext) {
            // converters: build X[buf^1] = tile t+1 (reg-direct LDG->cvt->STS, 2 rounds)
            const float* src = enc + (size_t)(t + 1)*TM*H;
            char* xn = smem_c + SM_X + (buf ^ 1)*32768;
            convert_half(src,        xn, 0,  ctid);
            convert_half(src + 8192, xn, 32, ctid);
        }

        // ---- segment boundary / final flush ----
        const bool newbat = hasnext && (((t + 1) >> 7) != curbat);
        if (!hasnext || newbat) {
            if (!isCv) g_cp[cta*2 + seg][ctid] = cacc;
            if (tid == 0) g_seg_s[cta*2 + seg] = s_run;
            if (newbat) {
                s_run = 0.f; cacc = make_float2(0.f, 0.f);
                seg = 1;
                curbat = (t + 1) >> 7;
                #pragma unroll
                for (int n = 0; n < 8; n++)
                    der[n] = __ldg((const float2*)g_dec_fea + curbat*128 + cw*32 + n*4 + lr);
            }
        }
    }
}

// ---------------- kernel 3: attn + new_cov (M=0, S from segment sums) ----------------
__global__ void __launch_bounds__(1024)
attn_kernel(const float* __restrict__ mask, const float* __restrict__ coverage,
            float* __restrict__ out)
{
    __shared__ float reds[32];
    __shared__ float sS;
    const int b = blockIdx.x, tid = threadIdx.x;
    const int lane = tid & 31, warp = tid >> 5;

    float s_i = 0.f;
    if (tid < NCTA) {
        const int i  = tid;
        const int si = (i*1024)/37, ei = ((i+1)*1024)/37;
        const int b0 = si >> 7, b1 = (ei - 1) >> 7;
        int sidx = -1;
        if (b0 == b) sidx = i*2;
        else if (b1 == b) sidx = i*2 + 1;
        if (sidx >= 0) s_i = g_seg_s[sidx];
    }
    #pragma unroll
    for (int o = 16; o; o >>= 1) s_i += __shfl_xor_sync(~0u, s_i, o);
    if (lane == 0) reds[warp] = s_i;
    __syncthreads();
    if (tid < 32) {
        float s2 = reds[tid];
        #pragma unroll
        for (int o = 16; o; o >>= 1) s2 += __shfl_xor_sync(~0u, s2, o);
        if (tid == 0) sS = s2;
    }
    __syncthreads();
    const float invS = 1.f / sS;

    const size_t boff = (size_t)b * TK;
    float* attn_out = out + BATCH*H;
    float* ncov_out = attn_out + (size_t)BATCH*TK;
    #pragma unroll
    for (int j = 0; j < 2; j++) {
        int i4 = tid + j*1024;
        float4 sv = __ldg((const float4*)(g_scores + boff) + i4);
        float4 mk = __ldg((const float4*)(mask + boff) + i4);
        float4 cv = __ldg((const float4*)(coverage + boff) + i4);
        float4 a;
        a.x = __expf(sv.x) * mk.x * invS;
        a.y = __expf(sv.y) * mk.y * invS;
        a.z = __expf(sv.z) * mk.z * invS;
        a.w = __expf(sv.w) * mk.w * invS;
        ((float4*)(attn_out + boff))[i4] = a;
        float4 nc;
        nc.x = fminf(fmaxf(cv.x + a.x, 0.f), 1.f);
        nc.y = fminf(fmaxf(cv.y + a.y, 0.f), 1.f);
        nc.z = fminf(fmaxf(cv.z + a.z, 0.f), 1.f);
        nc.w = fminf(fmaxf(cv.w + a.w, 0.f), 1.f);
        ((float4*)(ncov_out + boff))[i4] = nc;
    }
}

// ---------------- kernel 4: combine context partials -> c_t ----------------
__global__ void __launch_bounds__(256)
ct_combine(float* __restrict__ out)
{
    const int b = blockIdx.x, h = threadIdx.x;
    float S = 0.f, c = 0.f;
    for (int i = 0; i < NCTA; i++) {
        const int si = (i*1024)/37, ei = ((i+1)*1024)/37;
        const int b0 = si >> 7, b1 = (ei - 1) >> 7;
        int sidx = -1;
        if (b0 == b) sidx = i*2;
        else if (b1 == b) sidx = i*2 + 1;
        if (sidx >= 0) {
            S += g_seg_s[sidx];
            float2 cp = g_cp[sidx][h >> 1];
            c += (h & 1) ? cp.y : cp.x;
        }
    }
    out[(size_t)b*H + h] = c / S;
}

// ---------------- launch ----------------
extern "C" void kernel_launch(void* const* d_in, const int* in_sizes, int n_in,
                              void* d_out, int out_size)
{
    const float* s_t_hat = (const float*)d_in[0];
    const float* enc     = (const float*)d_in[1];
    const float* mask    = (const float*)d_in[2];
    const float* cov     = (const float*)d_in[3];
    const float* We      = (const float*)d_in[5];
    const float* Wd      = (const float*)d_in[6];
    const float* bd      = (const float*)d_in[7];
    const float* wc      = (const float*)d_in[8];
    const float* v       = (const float*)d_in[9];
    float* out = (float*)d_out;

    cudaFuncSetAttribute(scores_kernel, cudaFuncAttributeMaxDynamicSharedMemorySize, SMEM_TOTAL);

    dim3 gdec(BATCH, 8);
    dec_proj_kernel<<<gdec, 256>>>(s_t_hat, Wd, bd);   // launch 1
    dummy_kernel<<<1, 32>>>();                          // launch 2
    dummy_kernel2<<<1, 32>>>();                         // launch 3 (slot alignment)
    scores_kernel<<<NCTA, NTHREADS, SMEM_TOTAL>>>(enc, We, cov, mask, wc, v);  // launch 4 <- profiled
    attn_kernel<<<BATCH, 1024>>>(mask, cov, out);       // launch 5
    ct_combine<<<BATCH, 256>>>(out);                    // launch 6
}